// round 10
// baseline (speedup 1.0000x reference)
#include <cuda_runtime.h>
#include <math_constants.h>
#include <cstdint>

#define BS 8
#define NQ 1000
#define D 256
#define NROWS (BS * NQ)
#define TOPK 10
#define MAX_PAIRS (NROWS * TOPK)
#define MROWS 10      // rows per block in mask kernel
#define GROUP 32      // rows/pairs per group in GEMM kernels
#define XS 260        // floats per X row in shared (256 + 4 pad)
#define WS2 260       // floats per Ws k-row ((hi,lo)x128 + 4 pad)
#define KC 16         // k-values per staged chunk
#define NCHUNK (D / KC)
#define WBUF2 (KC * WS2)                 // floats per W half-buffer
#define GRID_G 444
#define SMEM_G ((GROUP * XS + 2 * WBUF2) * 4)   // 66,560 bytes

// ---------------- scratch (no allocations allowed) ----------------
__device__ float g_H[NROWS * D];        // layer-1 output (active rows)
__device__ float g_Z[NROWS * D];        // layer-2 output (pre-LN)
__device__ float g_P[NROWS * D];        // P = id_token @ W3
__device__ float g_cur[NROWS * D];      // running max of masked features
__device__ float g_Wsp[5 * 256 * 512];  // pre-split (hi,lo) weights, 512-stride rows
__device__ int   g_pairs[MAX_PAIRS * 2];
__device__ int   g_pair_count;
__device__ int   g_flag[NROWS];
__device__ int   g_idrows[NROWS];
__device__ int   g_nid;
__device__ int   g_outrows[NROWS];
__device__ int   g_nout;

__device__ __forceinline__ void atomicMaxFloat(float* addr, float v) {
    if (v >= 0.0f) atomicMax((int*)addr, __float_as_int(v));
    else           atomicMin((unsigned int*)addr, __float_as_uint(v));
}

// ---------------- tf32 split helpers ----------------
__device__ __forceinline__ void split_tf32(float x, float& hi, float& lo) {
    asm("cvt.rna.tf32.f32 %0, %1;" : "=f"(hi) : "f"(x));
    lo = x - hi;   // exact
}

// ---------------- cp.async helpers ----------------
__device__ __forceinline__ uint32_t smem_u32(const void* p) {
    return (uint32_t)__cvta_generic_to_shared(p);
}
__device__ __forceinline__ void cp16(uint32_t dst, const void* src) {
    asm volatile("cp.async.cg.shared.global [%0], [%1], 16;" :: "r"(dst), "l"(src));
}
__device__ __forceinline__ void cp_commit() {
    asm volatile("cp.async.commit_group;");
}
__device__ __forceinline__ void cp_wait0() {
    asm volatile("cp.async.wait_group 0;");
}

// ---------------- prep: reset counters/flags + split weights ----------------
__global__ __launch_bounds__(256) void k_prep(
    const float* __restrict__ W1, const float* __restrict__ W2,
    const float* __restrict__ W3, const float* __restrict__ W4,
    const float* __restrict__ W5)
{
    const int idx = blockIdx.x * 256 + threadIdx.x;
    if (idx < NROWS) g_flag[idx] = 0;
    if (idx == 0) { g_pair_count = 0; g_nid = 0; g_nout = 0; }
    if (idx < 5 * 65536) {
        const int w = idx >> 16, rem = idx & 65535;
        const float* Wt[5] = {W1, W2, W3, W4, W5};
        const float v = Wt[w][rem];
        float hi, lo; split_tf32(v, hi, lo);
        const int k = rem >> 8, n = rem & 255;
        float* dst = g_Wsp + ((size_t)(w * 256 + k) << 9) + (n << 1);
        dst[0] = hi; dst[1] = lo;
    }
}

__device__ __forceinline__ void mma_tf32(float c[4],
    uint32_t a0, uint32_t a1, uint32_t a2, uint32_t a3,
    uint32_t b0, uint32_t b1)
{
    asm volatile(
        "mma.sync.aligned.m16n8k8.row.col.f32.tf32.tf32.f32 "
        "{%0,%1,%2,%3}, {%4,%5,%6,%7}, {%8,%9}, {%0,%1,%2,%3};"
        : "+f"(c[0]), "+f"(c[1]), "+f"(c[2]), "+f"(c[3])
        : "r"(a0), "r"(a1), "r"(a2), "r"(a3), "r"(b0), "r"(b1));
}

// stage one 16-k chunk of one column-half of pre-split W via cp.async
__device__ __forceinline__ void stage_w_half(float* Wbuf, const float* __restrict__ Wsp,
                                             int kc, int ch, int t)
{
#pragma unroll
    for (int i = 0; i < 4; i++) {
        const int idx = t + (i << 8);        // 0..1023 16B segments
        const int row = idx >> 6;            // 0..15
        const int seg = idx & 63;            // 0..63
        cp16(smem_u32(Wbuf + row * WS2 + (seg << 2)),
             Wsp + (((size_t)(kc * KC + row)) << 9) + (ch << 8) + (seg << 2));
    }
    cp_commit();
}

// Core: C[4][4] = Xs(32 x 256, unsplit) @ W[:, ch*128 .. +128), 3xTF32.
// 8 warps: rg = w&1 (16-row group), cg = w>>1 (32-col group within the half).
__device__ __forceinline__ void mma_half(
    const float* Xs, float* Ws, const float* __restrict__ Wsp, int ch,
    float C[4][4], int rg, int cg, int g, int tig, int t)
{
#pragma unroll
    for (int nt = 0; nt < 4; nt++)
#pragma unroll
        for (int i = 0; i < 4; i++) C[nt][i] = 0.0f;

    const int row0 = rg * 16 + g;

    stage_w_half(Ws, Wsp, 0, ch, t);
    for (int kc = 0; kc < NCHUNK; kc++) {
        cp_wait0();
        __syncthreads();     // staged data visible; (kc=0) Xs writes ordered too
        if (kc + 1 < NCHUNK) stage_w_half(Ws + ((kc + 1) & 1) * WBUF2, Wsp, kc + 1, ch, t);
        const float* Wb = Ws + (kc & 1) * WBUF2;
#pragma unroll
        for (int ks = 0; ks < KC; ks += 8) {
            const int kk = kc * KC + ks + tig;
            const float a0f = Xs[row0 * XS + kk];
            const float a1f = Xs[(row0 + 8) * XS + kk];
            const float a2f = Xs[row0 * XS + kk + 4];
            const float a3f = Xs[(row0 + 8) * XS + kk + 4];
            float a0h,a0l,a1h,a1l,a2h,a2l,a3h,a3l;
            split_tf32(a0f,a0h,a0l); split_tf32(a1f,a1h,a1l);
            split_tf32(a2f,a2h,a2l); split_tf32(a3f,a3h,a3l);
            const uint32_t A0h=__float_as_uint(a0h), A0l=__float_as_uint(a0l);
            const uint32_t A1h=__float_as_uint(a1h), A1l=__float_as_uint(a1l);
            const uint32_t A2h=__float_as_uint(a2h), A2l=__float_as_uint(a2l);
            const uint32_t A3h=__float_as_uint(a3h), A3l=__float_as_uint(a3l);
#pragma unroll
            for (int nt = 0; nt < 4; nt++) {
                const int col = cg * 32 + nt * 8 + g;
                const float2 b0 = *(const float2*)(Wb + (ks + tig) * WS2 + (col << 1));
                const float2 b1 = *(const float2*)(Wb + (ks + tig + 4) * WS2 + (col << 1));
                const uint32_t B0h=__float_as_uint(b0.x), B0l=__float_as_uint(b0.y);
                const uint32_t B1h=__float_as_uint(b1.x), B1l=__float_as_uint(b1.y);
                mma_tf32(C[nt], A0h,A1h,A2h,A3h, B0h, B1h);
                mma_tf32(C[nt], A0h,A1h,A2h,A3h, B0l, B1l);
                mma_tf32(C[nt], A0l,A1l,A2l,A3l, B0h, B1h);
            }
        }
        __syncthreads();     // all warps done with this buffer before restage
    }
}

// stage 32 indexed rows (guarded) into Xs
__device__ __forceinline__ void stage_rows(float* Xs, const float* __restrict__ src,
                                           const int* srow, int t)
{
#pragma unroll
    for (int i = 0; i < 8; i++) {
        const int idx = t + (i << 8);
        const int r = idx >> 6, c4 = (idx & 63) << 2;
        const int rr = srow[r];
        const float4 v = (rr >= 0) ? *(const float4*)(src + (size_t)rr * D + c4)
                                   : make_float4(0.f, 0.f, 0.f, 0.f);
        *(float4*)(Xs + r * XS + c4) = v;
    }
}

// ---------------- K2: IoU mask + selection + cur-init + base output ----------------
__global__ __launch_bounds__(256) void k_mask_sel(
    const float* __restrict__ pred, const float* __restrict__ seed,
    const float* __restrict__ tgt,  const float* __restrict__ b5,
    float* __restrict__ out, float* __restrict__ out_mask)
{
    const int base = blockIdx.x * MROWS;
    const int b = base / NQ;
    const int t = threadIdx.x;

    __shared__ float4 s_box[NQ];
    __shared__ float  s_seed[NQ];
    __shared__ int    s_cnt, s_m;
    __shared__ float  sval[256];
    __shared__ int    sidx[256];

    const float rb5 = fmaxf(b5[t], 0.0f);

    for (int j = t; j < NQ; j += 256) {
        s_box[j]  = ((const float4*)pred)[b * NQ + j];
        s_seed[j] = seed[b * NQ + j];
    }
    __syncthreads();

    for (int r = 0; r < MROWS; r++) {
        const int row = base + r;
        const int li  = row - b * NQ;
        if (t == 0) s_cnt = 0;
        __syncthreads();

        const float4 pb = s_box[li];
        const float bx1 = __fsub_rn(pb.x, __fmul_rn(0.5f, pb.z));
        const float by1 = __fsub_rn(pb.y, __fmul_rn(0.5f, pb.w));
        const float bx2 = __fadd_rn(pb.x, __fmul_rn(0.5f, pb.z));
        const float by2 = __fadd_rn(pb.y, __fmul_rn(0.5f, pb.w));
        const float ai  = __fmul_rn(__fsub_rn(bx2, bx1), __fsub_rn(by2, by1));
        const bool negi = (s_seed[li] == 0.0f);

        for (int j = t; j < NQ; j += 256) {
            const float4 q = s_box[j];
            const float qx1 = __fsub_rn(q.x, __fmul_rn(0.5f, q.z));
            const float qy1 = __fsub_rn(q.y, __fmul_rn(0.5f, q.w));
            const float qx2 = __fadd_rn(q.x, __fmul_rn(0.5f, q.z));
            const float qy2 = __fadd_rn(q.y, __fmul_rn(0.5f, q.w));
            const float aj  = __fmul_rn(__fsub_rn(qx2, qx1), __fsub_rn(qy2, qy1));
            const float w = fmaxf(__fsub_rn(fminf(bx2, qx2), fmaxf(bx1, qx1)), 0.0f);
            const float h = fmaxf(__fsub_rn(fminf(by2, qy2), fmaxf(by1, qy1)), 0.0f);
            const float inter = __fmul_rn(w, h);
            const float uni = __fsub_rn(__fadd_rn(ai, aj), inter);
            const float iou = __fdiv_rn(inter, uni);
            const bool attn = (iou >= 0.5f);
            out_mask[(size_t)row * NQ + j] = attn ? 1.0f : 0.0f;
            if (attn && negi && (s_seed[j] != 0.0f)) {
                int p = atomicAdd(&s_cnt, 1);
                if (p < 256) { sval[p] = iou; sidx[p] = j; }
            }
        }
        __syncthreads();

        if (t == 0) {
            int cnt = min(s_cnt, 256);
            int m;
            int sel[TOPK];
            if (cnt <= TOPK) {
                m = cnt;
                for (int qq = 0; qq < cnt; qq++) sel[qq] = sidx[qq];
            } else {
                m = TOPK;
                for (int rr = 0; rr < TOPK; rr++) {
                    float best = -1.0f; int bj = 0x7fffffff; int bp = -1;
                    for (int p = 0; p < cnt; p++) {
                        float v = sval[p]; int j = sidx[p];
                        if (v > best || (v == best && j < bj)) { best = v; bj = j; bp = p; }
                    }
                    sel[rr] = bj;
                    sval[bp] = -1.0f;
                }
            }
            s_m = m;
            if (m > 0) {
                int pbase = atomicAdd(&g_pair_count, m);
                for (int qq = 0; qq < m; qq++) {
                    g_pairs[2 * (pbase + qq)]     = row;
                    g_pairs[2 * (pbase + qq) + 1] = sel[qq];
                    g_flag[b * NQ + sel[qq]] = 1;
                }
                g_flag[row] = 1;
                int op = atomicAdd(&g_nout, 1);
                g_outrows[op] = row;
            }
        }
        __syncthreads();
        const int m = s_m;
        if (m == 0) {
            const float neg = 1.0f - s_seed[li];
            out[(size_t)row * D + t] = tgt[(size_t)row * D + t] + rb5 * neg;
        } else {
            g_cur[(size_t)row * D + t] = (m < TOPK) ? 0.0f : -CUDART_INF_F;
        }
    }
}

// ---------------- compaction of id-rows ----------------
__global__ void k_compact() {
    const int i = blockIdx.x * 256 + threadIdx.x;
    if (i < NROWS && g_flag[i]) {
        int p = atomicAdd(&g_nid, 1);
        g_idrows[p] = i;
    }
}

// ---------------- L1: h = relu(tgt@W1 + b1) ----------------
__global__ __launch_bounds__(256, 3) void k_l1(
    const float* __restrict__ tgt, const float* __restrict__ b1)
{
    extern __shared__ float sm[];
    float* Xs = sm;
    float* Ws = sm + GROUP * XS;
    __shared__ int srow[GROUP];

    const int t = threadIdx.x;
    const int w = t >> 5, lane = t & 31;
    const int rg = w & 1, cg = w >> 1;
    const int g = lane >> 2, tig = lane & 3;
    const int nact = g_nid;
    const int units = ((nact + GROUP - 1) / GROUP) * 2;

    for (int u = blockIdx.x; u < units; u += gridDim.x) {
        const int g0 = (u >> 1) * GROUP;
        const int ch = u & 1;
        if (t < GROUP) srow[t] = (g0 + t < nact) ? g_idrows[g0 + t] : -1;
        __syncthreads();
        stage_rows(Xs, tgt, srow, t);

        float C[4][4];
        mma_half(Xs, Ws, g_Wsp, ch, C, rg, cg, g, tig, t);

#pragma unroll
        for (int nt = 0; nt < 4; nt++) {
            const int col = ch * 128 + cg * 32 + nt * 8 + (tig << 1);
            const float2 bb = *(const float2*)(b1 + col);
            const int r0 = rg * 16 + g, r1 = r0 + 8;
            const int rw0 = srow[r0], rw1 = srow[r1];
            if (rw0 >= 0)
                *(float2*)(g_H + (size_t)rw0 * D + col) =
                    make_float2(fmaxf(C[nt][0] + bb.x, 0.f), fmaxf(C[nt][1] + bb.y, 0.f));
            if (rw1 >= 0)
                *(float2*)(g_H + (size_t)rw1 * D + col) =
                    make_float2(fmaxf(C[nt][2] + bb.x, 0.f), fmaxf(C[nt][3] + bb.y, 0.f));
        }
        __syncthreads();
    }
}

// ---------------- L2: z = h@W2 + b2 ----------------
__global__ __launch_bounds__(256, 3) void k_l2(const float* __restrict__ b2)
{
    extern __shared__ float sm[];
    float* Xs = sm;
    float* Ws = sm + GROUP * XS;
    __shared__ int srow[GROUP];

    const int t = threadIdx.x;
    const int w = t >> 5, lane = t & 31;
    const int rg = w & 1, cg = w >> 1;
    const int g = lane >> 2, tig = lane & 3;
    const int nact = g_nid;
    const int units = ((nact + GROUP - 1) / GROUP) * 2;
    const float* W2sp = g_Wsp + (1 << 17);

    for (int u = blockIdx.x; u < units; u += gridDim.x) {
        const int g0 = (u >> 1) * GROUP;
        const int ch = u & 1;
        if (t < GROUP) srow[t] = (g0 + t < nact) ? g_idrows[g0 + t] : -1;
        __syncthreads();
        stage_rows(Xs, g_H, srow, t);

        float C[4][4];
        mma_half(Xs, Ws, W2sp, ch, C, rg, cg, g, tig, t);

#pragma unroll
        for (int nt = 0; nt < 4; nt++) {
            const int col = ch * 128 + cg * 32 + nt * 8 + (tig << 1);
            const float2 bb = *(const float2*)(b2 + col);
            const int r0 = rg * 16 + g, r1 = r0 + 8;
            const int rw0 = srow[r0], rw1 = srow[r1];
            if (rw0 >= 0)
                *(float2*)(g_Z + (size_t)rw0 * D + col) =
                    make_float2(C[nt][0] + bb.x, C[nt][1] + bb.y);
            if (rw1 >= 0)
                *(float2*)(g_Z + (size_t)rw1 * D + col) =
                    make_float2(C[nt][2] + bb.x, C[nt][3] + bb.y);
        }
        __syncthreads();
    }
}

// ---------------- L3: P = (LN(z)*g2+be2) @ W3 ----------------
__global__ __launch_bounds__(256, 3) void k_l3(
    const float* __restrict__ g2, const float* __restrict__ be2)
{
    extern __shared__ float sm[];
    float* Xs = sm;
    float* Ws = sm + GROUP * XS;
    __shared__ int srow[GROUP];
    __shared__ float s_mean[GROUP], s_rstd[GROUP];

    const int t = threadIdx.x;
    const int w = t >> 5, lane = t & 31;
    const int rg = w & 1, cg = w >> 1;
    const int g = lane >> 2, tig = lane & 3;
    const int nact = g_nid;
    const int units = ((nact + GROUP - 1) / GROUP) * 2;
    const float* W3sp = g_Wsp + (2 << 17);
    const float gv = g2[t], bev = be2[t];

    for (int u = blockIdx.x; u < units; u += gridDim.x) {
        const int g0 = (u >> 1) * GROUP;
        const int ch = u & 1;
        if (t < GROUP) srow[t] = (g0 + t < nact) ? g_idrows[g0 + t] : -1;
        __syncthreads();
        stage_rows(Xs, g_Z, srow, t);
        __syncthreads();

        // LN stats: warp w handles rows 4w..4w+3
        for (int rr = (w << 2); rr < (w << 2) + 4; rr++) {
            float s = 0.f, sq = 0.f;
            for (int c = lane; c < D; c += 32) {
                const float z = Xs[rr * XS + c];
                s += z; sq += z * z;
            }
#pragma unroll
            for (int off = 16; off > 0; off >>= 1) {
                s  += __shfl_down_sync(0xffffffff, s,  off);
                sq += __shfl_down_sync(0xffffffff, sq, off);
            }
            if (lane == 0) {
                const float m = s * (1.0f / D);
                s_mean[rr] = m;
                s_rstd[rr] = rsqrtf(sq * (1.0f / D) - m * m + 1e-5f);
            }
        }
        __syncthreads();
#pragma unroll 4
        for (int r = 0; r < GROUP; r++) {
            const float z = Xs[r * XS + t];
            Xs[r * XS + t] = (z - s_mean[r]) * s_rstd[r] * gv + bev;
        }
        // no sync needed: mma_half's first internal barrier orders these writes

        float C[4][4];
        mma_half(Xs, Ws, W3sp, ch, C, rg, cg, g, tig, t);

#pragma unroll
        for (int nt = 0; nt < 4; nt++) {
            const int col = ch * 128 + cg * 32 + nt * 8 + (tig << 1);
            const int r0 = rg * 16 + g, r1 = r0 + 8;
            const int rw0 = srow[r0], rw1 = srow[r1];
            if (rw0 >= 0)
                *(float2*)(g_P + (size_t)rw0 * D + col) = make_float2(C[nt][0], C[nt][1]);
            if (rw1 >= 0)
                *(float2*)(g_P + (size_t)rw1 * D + col) = make_float2(C[nt][2], C[nt][3]);
        }
        __syncthreads();
    }
}

// ---------------- L4: per-pair relu(P_i-P_j+b3)@W4+b4 -> seg-max + atomic ----------------
__global__ __launch_bounds__(256, 3) void k_l4(
    const float* __restrict__ b3, const float* __restrict__ b4)
{
    extern __shared__ float sm[];
    float* Xs = sm;
    float* Ws = sm + GROUP * XS;
    __shared__ int spr[GROUP], sjj[GROUP];

    const int t = threadIdx.x;
    const int w = t >> 5, lane = t & 31;
    const int rg = w & 1, cg = w >> 1;
    const int g = lane >> 2, tig = lane & 3;
    const int npairs = g_pair_count;
    const int units = ((npairs + GROUP - 1) / GROUP) * 2;
    const float* W4sp = g_Wsp + (3 << 17);

    for (int u = blockIdx.x; u < units; u += gridDim.x) {
        const int g0 = (u >> 1) * GROUP;
        const int ch = u & 1;
        if (t < GROUP) {
            if (g0 + t < npairs) {
                spr[t] = g_pairs[2 * (g0 + t)];
                sjj[t] = g_pairs[2 * (g0 + t) + 1];
            } else spr[t] = -1;
        }
        __syncthreads();

        // stage X = relu(P_i - P_j + b3) (full width)
#pragma unroll
        for (int i = 0; i < 8; i++) {
            const int idx = t + (i << 8);
            const int p = idx >> 6, c4 = (idx & 63) << 2;
            const int rp = spr[p];
            float4 v = make_float4(0.f, 0.f, 0.f, 0.f);
            if (rp >= 0) {
                const int jab = (rp / NQ) * NQ + sjj[p];
                const float4 a  = *(const float4*)(g_P + (size_t)rp  * D + c4);
                const float4 nb = *(const float4*)(g_P + (size_t)jab * D + c4);
                const float4 bv = *(const float4*)(b3 + c4);
                v.x = fmaxf(a.x - nb.x + bv.x, 0.f);
                v.y = fmaxf(a.y - nb.y + bv.y, 0.f);
                v.z = fmaxf(a.z - nb.z + bv.z, 0.f);
                v.w = fmaxf(a.w - nb.w + bv.w, 0.f);
            }
            *(float4*)(Xs + p * XS + c4) = v;
        }

        float C[4][4];
        mma_half(Xs, Ws, W4sp, ch, C, rg, cg, g, tig, t);

        // dump features into Xs (local col index within the half)
#pragma unroll
        for (int nt = 0; nt < 4; nt++) {
            const int colL = cg * 32 + nt * 8 + (tig << 1);
            const int p0 = rg * 16 + g, p1 = p0 + 8;
            *(float2*)(Xs + p0 * XS + colL) = make_float2(C[nt][0], C[nt][1]);
            *(float2*)(Xs + p1 * XS + colL) = make_float2(C[nt][2], C[nt][3]);
        }
        __syncthreads();

        // segmented max: thread t -> local col t&127, pair-range half t>>7
        {
            const int cL = t & 127;
            const int colG = ch * 128 + cL;
            const float bias = b4[colG];
            const int pLo = (t >> 7) << 4;      // 0 or 16
            int curRow = -1; float curMax = 0.f;
            for (int p = pLo; p < pLo + 16; p++) {
                const int rp = spr[p];
                if (rp < 0) break;
                const float v = Xs[p * XS + cL] + bias;
                if (rp != curRow) {
                    if (curRow >= 0) atomicMaxFloat(&g_cur[(size_t)curRow * D + colG], curMax);
                    curRow = rp; curMax = v;
                } else {
                    curMax = fmaxf(curMax, v);
                }
            }
            if (curRow >= 0) atomicMaxFloat(&g_cur[(size_t)curRow * D + colG], curMax);
        }
        __syncthreads();
    }
}

// ---------------- L5: out = tgt + relu(cur@W5+b5) for active rows ----------------
__global__ __launch_bounds__(256, 3) void k_l5(
    const float* __restrict__ tgt, const float* __restrict__ b5,
    float* __restrict__ out)
{
    extern __shared__ float sm[];
    float* Xs = sm;
    float* Ws = sm + GROUP * XS;
    __shared__ int srow[GROUP];

    const int t = threadIdx.x;
    const int w = t >> 5, lane = t & 31;
    const int rg = w & 1, cg = w >> 1;
    const int g = lane >> 2, tig = lane & 3;
    const int nact = g_nout;
    const int units = ((nact + GROUP - 1) / GROUP) * 2;
    const float* W5sp = g_Wsp + (4 << 17);

    for (int u = blockIdx.x; u < units; u += gridDim.x) {
        const int g0 = (u >> 1) * GROUP;
        const int ch = u & 1;
        if (t < GROUP) srow[t] = (g0 + t < nact) ? g_outrows[g0 + t] : -1;
        __syncthreads();
        stage_rows(Xs, g_cur, srow, t);

        float C[4][4];
        mma_half(Xs, Ws, W5sp, ch, C, rg, cg, g, tig, t);

#pragma unroll
        for (int nt = 0; nt < 4; nt++) {
            const int col = ch * 128 + cg * 32 + nt * 8 + (tig << 1);
            const float2 bb = *(const float2*)(b5 + col);
            const int r0 = rg * 16 + g, r1 = r0 + 8;
            const int rw0 = srow[r0], rw1 = srow[r1];
            if (rw0 >= 0) {
                const float2 tg = *(const float2*)(tgt + (size_t)rw0 * D + col);
                *(float2*)(out + (size_t)rw0 * D + col) =
                    make_float2(tg.x + fmaxf(C[nt][0] + bb.x, 0.f),
                                tg.y + fmaxf(C[nt][1] + bb.y, 0.f));
            }
            if (rw1 >= 0) {
                const float2 tg = *(const float2*)(tgt + (size_t)rw1 * D + col);
                *(float2*)(out + (size_t)rw1 * D + col) =
                    make_float2(tg.x + fmaxf(C[nt][2] + bb.x, 0.f),
                                tg.y + fmaxf(C[nt][3] + bb.y, 0.f));
            }
        }
        __syncthreads();
    }
}

// ---------------- launch ----------------
extern "C" void kernel_launch(void* const* d_in, const int* in_sizes, int n_in,
                              void* d_out, int out_size) {
    const float* tgt  = (const float*)d_in[0];
    const float* seed = (const float*)d_in[1];
    const float* pred = (const float*)d_in[2];
    const float* W1 = (const float*)d_in[3];  const float* b1 = (const float*)d_in[4];
    const float* W2 = (const float*)d_in[5];  const float* b2 = (const float*)d_in[6];
    const float* g2 = (const float*)d_in[7];  const float* be2 = (const float*)d_in[8];
    const float* W3 = (const float*)d_in[9];  const float* b3 = (const float*)d_in[10];
    const float* W4 = (const float*)d_in[11]; const float* b4 = (const float*)d_in[12];
    const float* W5 = (const float*)d_in[13]; const float* b5 = (const float*)d_in[14];

    float* out = (float*)d_out;                 // cur_tgt: 8*1000*256 floats
    float* out_mask = out + (size_t)NROWS * D;  // attn_mask: 8*1000*1000 floats

    cudaFuncSetAttribute(k_l1, cudaFuncAttributeMaxDynamicSharedMemorySize, SMEM_G);
    cudaFuncSetAttribute(k_l2, cudaFuncAttributeMaxDynamicSharedMemorySize, SMEM_G);
    cudaFuncSetAttribute(k_l3, cudaFuncAttributeMaxDynamicSharedMemorySize, SMEM_G);
    cudaFuncSetAttribute(k_l4, cudaFuncAttributeMaxDynamicSharedMemorySize, SMEM_G);
    cudaFuncSetAttribute(k_l5, cudaFuncAttributeMaxDynamicSharedMemorySize, SMEM_G);

    k_prep<<<(5 * 65536 + 255) / 256, 256>>>(W1, W2, W3, W4, W5);
    k_mask_sel<<<NROWS / MROWS, 256>>>(pred, seed, tgt, b5, out, out_mask);
    k_compact<<<(NROWS + 255) / 256, 256>>>();
    k_l1<<<GRID_G, 256, SMEM_G>>>(tgt, b1);
    k_l2<<<GRID_G, 256, SMEM_G>>>(b2);
    k_l3<<<GRID_G, 256, SMEM_G>>>(g2, be2);
    k_l4<<<GRID_G, 256, SMEM_G>>>(b3, b4);
    k_l5<<<GRID_G, 256, SMEM_G>>>(tgt, b5, out);
}

// round 11
// speedup vs baseline: 1.1333x; 1.1333x over previous
#include <cuda_runtime.h>
#include <math_constants.h>
#include <cstdint>

#define BS 8
#define NQ 1000
#define D 256
#define NROWS (BS * NQ)
#define TOPK 10
#define MAX_PAIRS (NROWS * TOPK)
#define MROWS 10      // rows per block in mask kernel
#define GROUP 32      // rows/pairs per group in GEMM kernels
#define XS 260        // floats per X row in shared (256 + 4 pad)
#define WSU 136       // floats per W k-row in shared (128 + 8 pad -> conflict-free)
#define KC 16         // k-values per staged chunk
#define NCHUNK (D / KC)
#define WBUFU (KC * WSU)                 // floats per W buffer (2176)
#define GRID_G 444
#define SMEM_G ((GROUP * XS + 3 * WBUFU) * 4)   // 59,392 bytes

// ---------------- scratch (no allocations allowed) ----------------
__device__ float g_H[NROWS * D];        // layer-1 output (active rows)
__device__ float g_Z[NROWS * D];        // layer-2 output (pre-LN)
__device__ float g_P[NROWS * D];        // P = id_token @ W3
__device__ float g_cur[NROWS * D];      // running max of masked features
__device__ int   g_pairs[MAX_PAIRS * 2];
__device__ int   g_pair_count;
__device__ int   g_flag[NROWS];
__device__ int   g_idrows[NROWS];
__device__ int   g_nid;
__device__ int   g_outrows[NROWS];
__device__ int   g_nout;

__device__ __forceinline__ void atomicMaxFloat(float* addr, float v) {
    if (v >= 0.0f) atomicMax((int*)addr, __float_as_int(v));
    else           atomicMin((unsigned int*)addr, __float_as_uint(v));
}

// ---------------- tf32 split helper ----------------
__device__ __forceinline__ void split_tf32(float x, float& hi, float& lo) {
    asm("cvt.rna.tf32.f32 %0, %1;" : "=f"(hi) : "f"(x));
    lo = x - hi;   // exact
}

// ---------------- cp.async helpers ----------------
__device__ __forceinline__ uint32_t smem_u32(const void* p) {
    return (uint32_t)__cvta_generic_to_shared(p);
}
__device__ __forceinline__ void cp16(uint32_t dst, const void* src) {
    asm volatile("cp.async.cg.shared.global [%0], [%1], 16;" :: "r"(dst), "l"(src));
}
__device__ __forceinline__ void cp_commit() {
    asm volatile("cp.async.commit_group;");
}
__device__ __forceinline__ void cp_wait0() {
    asm volatile("cp.async.wait_group 0;");
}
__device__ __forceinline__ void cp_wait1() {
    asm volatile("cp.async.wait_group 1;");
}

// ---------------- prep: reset counters/flags ----------------
__global__ __launch_bounds__(256) void k_prep() {
    const int idx = blockIdx.x * 256 + threadIdx.x;
    if (idx < NROWS) g_flag[idx] = 0;
    if (idx == 0) { g_pair_count = 0; g_nid = 0; g_nout = 0; }
}

__device__ __forceinline__ void mma_tf32(float c[4],
    uint32_t a0, uint32_t a1, uint32_t a2, uint32_t a3,
    uint32_t b0, uint32_t b1)
{
    asm volatile(
        "mma.sync.aligned.m16n8k8.row.col.f32.tf32.tf32.f32 "
        "{%0,%1,%2,%3}, {%4,%5,%6,%7}, {%8,%9}, {%0,%1,%2,%3};"
        : "+f"(c[0]), "+f"(c[1]), "+f"(c[2]), "+f"(c[3])
        : "r"(a0), "r"(a1), "r"(a2), "r"(a3), "r"(b0), "r"(b1));
}

// stage one 16-k chunk of one column-half of W (unsplit) via cp.async
// 16 rows x 128 floats = 512 float4 over 256 threads (2 each)
__device__ __forceinline__ void stage_w_half(float* Wbuf, const float* __restrict__ Wg,
                                             int kc, int ch, int t)
{
#pragma unroll
    for (int i = 0; i < 2; i++) {
        const int idx = t + (i << 8);        // 0..511
        const int row = idx >> 5;            // 0..15
        const int seg = idx & 31;            // 0..31
        cp16(smem_u32(Wbuf + row * WSU + (seg << 2)),
             Wg + (size_t)(kc * KC + row) * D + (ch << 7) + (seg << 2));
    }
    cp_commit();
}

// Core: C[4][4] = Xs(32 x 256, unsplit) @ W[:, ch*128 .. +128), 3xTF32.
// 8 warps: rg = w&1 (16-row group), cg = w>>1 (32-col group within the half).
// W staged unsplit via 3-deep cp.async pipeline; B fragments split in registers.
__device__ __forceinline__ void mma_half(
    const float* Xs, float* Ws, const float* __restrict__ Wg, int ch,
    float C[4][4], int rg, int cg, int g, int tig, int t)
{
#pragma unroll
    for (int nt = 0; nt < 4; nt++)
#pragma unroll
        for (int i = 0; i < 4; i++) C[nt][i] = 0.0f;

    const int row0 = rg * 16 + g;

    stage_w_half(Ws,          Wg, 0, ch, t);
    stage_w_half(Ws + WBUFU,  Wg, 1, ch, t);
    for (int kc = 0; kc < NCHUNK; kc++) {
        if (kc == NCHUNK - 1) cp_wait0(); else cp_wait1();
        __syncthreads();     // chunk kc visible; all warps done with buffer being restaged
        if (kc + 2 < NCHUNK) stage_w_half(Ws + ((kc + 2) % 3) * WBUFU, Wg, kc + 2, ch, t);
        const float* Wb = Ws + (kc % 3) * WBUFU;
#pragma unroll
        for (int ks = 0; ks < KC; ks += 8) {
            const int kk = kc * KC + ks + tig;
            const float a0f = Xs[row0 * XS + kk];
            const float a1f = Xs[(row0 + 8) * XS + kk];
            const float a2f = Xs[row0 * XS + kk + 4];
            const float a3f = Xs[(row0 + 8) * XS + kk + 4];
            float a0h,a0l,a1h,a1l,a2h,a2l,a3h,a3l;
            split_tf32(a0f,a0h,a0l); split_tf32(a1f,a1h,a1l);
            split_tf32(a2f,a2h,a2l); split_tf32(a3f,a3h,a3l);
            const uint32_t A0h=__float_as_uint(a0h), A0l=__float_as_uint(a0l);
            const uint32_t A1h=__float_as_uint(a1h), A1l=__float_as_uint(a1l);
            const uint32_t A2h=__float_as_uint(a2h), A2l=__float_as_uint(a2l);
            const uint32_t A3h=__float_as_uint(a3h), A3l=__float_as_uint(a3l);
#pragma unroll
            for (int nt = 0; nt < 4; nt++) {
                const int col = cg * 32 + nt * 8 + g;
                const float w0 = Wb[(ks + tig) * WSU + col];
                const float w1 = Wb[(ks + tig + 4) * WSU + col];
                float b0h,b0l,b1h,b1l;
                split_tf32(w0,b0h,b0l); split_tf32(w1,b1h,b1l);
                const uint32_t B0h=__float_as_uint(b0h), B0l=__float_as_uint(b0l);
                const uint32_t B1h=__float_as_uint(b1h), B1l=__float_as_uint(b1l);
                mma_tf32(C[nt], A0h,A1h,A2h,A3h, B0h, B1h);
                mma_tf32(C[nt], A0h,A1h,A2h,A3h, B0l, B1l);
                mma_tf32(C[nt], A0l,A1l,A2l,A3l, B0h, B1h);
            }
        }
    }
    __syncthreads();   // all warps done with last buffer before caller reuses Xs/Ws
}

// stage 32 indexed rows (guarded) into Xs
__device__ __forceinline__ void stage_rows(float* Xs, const float* __restrict__ src,
                                           const int* srow, int t)
{
#pragma unroll
    for (int i = 0; i < 8; i++) {
        const int idx = t + (i << 8);
        const int r = idx >> 6, c4 = (idx & 63) << 2;
        const int rr = srow[r];
        const float4 v = (rr >= 0) ? *(const float4*)(src + (size_t)rr * D + c4)
                                   : make_float4(0.f, 0.f, 0.f, 0.f);
        *(float4*)(Xs + r * XS + c4) = v;
    }
}

// ---------------- K2: IoU mask + selection + cur-init + base output ----------------
__global__ __launch_bounds__(256) void k_mask_sel(
    const float* __restrict__ pred, const float* __restrict__ seed,
    const float* __restrict__ tgt,  const float* __restrict__ b5,
    float* __restrict__ out, float* __restrict__ out_mask)
{
    const int base = blockIdx.x * MROWS;
    const int b = base / NQ;
    const int t = threadIdx.x;

    __shared__ float4 s_box[NQ];
    __shared__ float  s_seed[NQ];
    __shared__ int    s_cnt, s_m;
    __shared__ float  sval[256];
    __shared__ int    sidx[256];

    const float rb5 = fmaxf(b5[t], 0.0f);

    for (int j = t; j < NQ; j += 256) {
        s_box[j]  = ((const float4*)pred)[b * NQ + j];
        s_seed[j] = seed[b * NQ + j];
    }
    __syncthreads();

    for (int r = 0; r < MROWS; r++) {
        const int row = base + r;
        const int li  = row - b * NQ;
        if (t == 0) s_cnt = 0;
        __syncthreads();

        const float4 pb = s_box[li];
        const float bx1 = __fsub_rn(pb.x, __fmul_rn(0.5f, pb.z));
        const float by1 = __fsub_rn(pb.y, __fmul_rn(0.5f, pb.w));
        const float bx2 = __fadd_rn(pb.x, __fmul_rn(0.5f, pb.z));
        const float by2 = __fadd_rn(pb.y, __fmul_rn(0.5f, pb.w));
        const float ai  = __fmul_rn(__fsub_rn(bx2, bx1), __fsub_rn(by2, by1));
        const bool negi = (s_seed[li] == 0.0f);

        for (int j = t; j < NQ; j += 256) {
            const float4 q = s_box[j];
            const float qx1 = __fsub_rn(q.x, __fmul_rn(0.5f, q.z));
            const float qy1 = __fsub_rn(q.y, __fmul_rn(0.5f, q.w));
            const float qx2 = __fadd_rn(q.x, __fmul_rn(0.5f, q.z));
            const float qy2 = __fadd_rn(q.y, __fmul_rn(0.5f, q.w));
            const float aj  = __fmul_rn(__fsub_rn(qx2, qx1), __fsub_rn(qy2, qy1));
            const float w = fmaxf(__fsub_rn(fminf(bx2, qx2), fmaxf(bx1, qx1)), 0.0f);
            const float h = fmaxf(__fsub_rn(fminf(by2, qy2), fmaxf(by1, qy1)), 0.0f);
            const float inter = __fmul_rn(w, h);
            const float uni = __fsub_rn(__fadd_rn(ai, aj), inter);
            const float iou = __fdiv_rn(inter, uni);
            const bool attn = (iou >= 0.5f);
            out_mask[(size_t)row * NQ + j] = attn ? 1.0f : 0.0f;
            if (attn && negi && (s_seed[j] != 0.0f)) {
                int p = atomicAdd(&s_cnt, 1);
                if (p < 256) { sval[p] = iou; sidx[p] = j; }
            }
        }
        __syncthreads();

        if (t == 0) {
            int cnt = min(s_cnt, 256);
            int m;
            int sel[TOPK];
            if (cnt <= TOPK) {
                m = cnt;
                for (int qq = 0; qq < cnt; qq++) sel[qq] = sidx[qq];
            } else {
                m = TOPK;
                for (int rr = 0; rr < TOPK; rr++) {
                    float best = -1.0f; int bj = 0x7fffffff; int bp = -1;
                    for (int p = 0; p < cnt; p++) {
                        float v = sval[p]; int j = sidx[p];
                        if (v > best || (v == best && j < bj)) { best = v; bj = j; bp = p; }
                    }
                    sel[rr] = bj;
                    sval[bp] = -1.0f;
                }
            }
            s_m = m;
            if (m > 0) {
                int pbase = atomicAdd(&g_pair_count, m);
                for (int qq = 0; qq < m; qq++) {
                    g_pairs[2 * (pbase + qq)]     = row;
                    g_pairs[2 * (pbase + qq) + 1] = sel[qq];
                    g_flag[b * NQ + sel[qq]] = 1;
                }
                g_flag[row] = 1;
                int op = atomicAdd(&g_nout, 1);
                g_outrows[op] = row;
            }
        }
        __syncthreads();
        const int m = s_m;
        if (m == 0) {
            const float neg = 1.0f - s_seed[li];
            out[(size_t)row * D + t] = tgt[(size_t)row * D + t] + rb5 * neg;
        } else {
            g_cur[(size_t)row * D + t] = (m < TOPK) ? 0.0f : -CUDART_INF_F;
        }
    }
}

// ---------------- compaction of id-rows ----------------
__global__ void k_compact() {
    const int i = blockIdx.x * 256 + threadIdx.x;
    if (i < NROWS && g_flag[i]) {
        int p = atomicAdd(&g_nid, 1);
        g_idrows[p] = i;
    }
}

// ---------------- L1: h = relu(tgt@W1 + b1) ----------------
__global__ __launch_bounds__(256, 3) void k_l1(
    const float* __restrict__ tgt, const float* __restrict__ W1,
    const float* __restrict__ b1)
{
    extern __shared__ float sm[];
    float* Xs = sm;
    float* Ws = sm + GROUP * XS;
    __shared__ int srow[GROUP];

    const int t = threadIdx.x;
    const int w = t >> 5, lane = t & 31;
    const int rg = w & 1, cg = w >> 1;
    const int g = lane >> 2, tig = lane & 3;
    const int nact = g_nid;
    const int units = ((nact + GROUP - 1) / GROUP) * 2;

    for (int u = blockIdx.x; u < units; u += gridDim.x) {
        const int g0 = (u >> 1) * GROUP;
        const int ch = u & 1;
        if (t < GROUP) srow[t] = (g0 + t < nact) ? g_idrows[g0 + t] : -1;
        __syncthreads();
        stage_rows(Xs, tgt, srow, t);

        float C[4][4];
        mma_half(Xs, Ws, W1, ch, C, rg, cg, g, tig, t);

#pragma unroll
        for (int nt = 0; nt < 4; nt++) {
            const int col = ch * 128 + cg * 32 + nt * 8 + (tig << 1);
            const float2 bb = *(const float2*)(b1 + col);
            const int r0 = rg * 16 + g, r1 = r0 + 8;
            const int rw0 = srow[r0], rw1 = srow[r1];
            if (rw0 >= 0)
                *(float2*)(g_H + (size_t)rw0 * D + col) =
                    make_float2(fmaxf(C[nt][0] + bb.x, 0.f), fmaxf(C[nt][1] + bb.y, 0.f));
            if (rw1 >= 0)
                *(float2*)(g_H + (size_t)rw1 * D + col) =
                    make_float2(fmaxf(C[nt][2] + bb.x, 0.f), fmaxf(C[nt][3] + bb.y, 0.f));
        }
        __syncthreads();
    }
}

// ---------------- L2: z = h@W2 + b2 ----------------
__global__ __launch_bounds__(256, 3) void k_l2(
    const float* __restrict__ W2, const float* __restrict__ b2)
{
    extern __shared__ float sm[];
    float* Xs = sm;
    float* Ws = sm + GROUP * XS;
    __shared__ int srow[GROUP];

    const int t = threadIdx.x;
    const int w = t >> 5, lane = t & 31;
    const int rg = w & 1, cg = w >> 1;
    const int g = lane >> 2, tig = lane & 3;
    const int nact = g_nid;
    const int units = ((nact + GROUP - 1) / GROUP) * 2;

    for (int u = blockIdx.x; u < units; u += gridDim.x) {
        const int g0 = (u >> 1) * GROUP;
        const int ch = u & 1;
        if (t < GROUP) srow[t] = (g0 + t < nact) ? g_idrows[g0 + t] : -1;
        __syncthreads();
        stage_rows(Xs, g_H, srow, t);

        float C[4][4];
        mma_half(Xs, Ws, W2, ch, C, rg, cg, g, tig, t);

#pragma unroll
        for (int nt = 0; nt < 4; nt++) {
            const int col = ch * 128 + cg * 32 + nt * 8 + (tig << 1);
            const float2 bb = *(const float2*)(b2 + col);
            const int r0 = rg * 16 + g, r1 = r0 + 8;
            const int rw0 = srow[r0], rw1 = srow[r1];
            if (rw0 >= 0)
                *(float2*)(g_Z + (size_t)rw0 * D + col) =
                    make_float2(C[nt][0] + bb.x, C[nt][1] + bb.y);
            if (rw1 >= 0)
                *(float2*)(g_Z + (size_t)rw1 * D + col) =
                    make_float2(C[nt][2] + bb.x, C[nt][3] + bb.y);
        }
        __syncthreads();
    }
}

// ---------------- L3: P = (LN(z)*g2+be2) @ W3 ----------------
__global__ __launch_bounds__(256, 3) void k_l3(
    const float* __restrict__ W3,
    const float* __restrict__ g2, const float* __restrict__ be2)
{
    extern __shared__ float sm[];
    float* Xs = sm;
    float* Ws = sm + GROUP * XS;
    __shared__ int srow[GROUP];
    __shared__ float s_mean[GROUP], s_rstd[GROUP];

    const int t = threadIdx.x;
    const int w = t >> 5, lane = t & 31;
    const int rg = w & 1, cg = w >> 1;
    const int g = lane >> 2, tig = lane & 3;
    const int nact = g_nid;
    const int units = ((nact + GROUP - 1) / GROUP) * 2;
    const float gv = g2[t], bev = be2[t];

    for (int u = blockIdx.x; u < units; u += gridDim.x) {
        const int g0 = (u >> 1) * GROUP;
        const int ch = u & 1;
        if (t < GROUP) srow[t] = (g0 + t < nact) ? g_idrows[g0 + t] : -1;
        __syncthreads();
        stage_rows(Xs, g_Z, srow, t);
        __syncthreads();

        // LN stats: warp w handles rows 4w..4w+3
        for (int rr = (w << 2); rr < (w << 2) + 4; rr++) {
            float s = 0.f, sq = 0.f;
            for (int c = lane; c < D; c += 32) {
                const float z = Xs[rr * XS + c];
                s += z; sq += z * z;
            }
#pragma unroll
            for (int off = 16; off > 0; off >>= 1) {
                s  += __shfl_down_sync(0xffffffff, s,  off);
                sq += __shfl_down_sync(0xffffffff, sq, off);
            }
            if (lane == 0) {
                const float m = s * (1.0f / D);
                s_mean[rr] = m;
                s_rstd[rr] = rsqrtf(sq * (1.0f / D) - m * m + 1e-5f);
            }
        }
        __syncthreads();
#pragma unroll 4
        for (int r = 0; r < GROUP; r++) {
            const float z = Xs[r * XS + t];
            Xs[r * XS + t] = (z - s_mean[r]) * s_rstd[r] * gv + bev;
        }
        // mma_half's first internal barrier orders these writes

        float C[4][4];
        mma_half(Xs, Ws, W3, ch, C, rg, cg, g, tig, t);

#pragma unroll
        for (int nt = 0; nt < 4; nt++) {
            const int col = ch * 128 + cg * 32 + nt * 8 + (tig << 1);
            const int r0 = rg * 16 + g, r1 = r0 + 8;
            const int rw0 = srow[r0], rw1 = srow[r1];
            if (rw0 >= 0)
                *(float2*)(g_P + (size_t)rw0 * D + col) = make_float2(C[nt][0], C[nt][1]);
            if (rw1 >= 0)
                *(float2*)(g_P + (size_t)rw1 * D + col) = make_float2(C[nt][2], C[nt][3]);
        }
        __syncthreads();
    }
}

// ---------------- L4: per-pair relu(P_i-P_j+b3)@W4+b4 -> seg-max + atomic ----------------
__global__ __launch_bounds__(256, 3) void k_l4(
    const float* __restrict__ W4,
    const float* __restrict__ b3, const float* __restrict__ b4)
{
    extern __shared__ float sm[];
    float* Xs = sm;
    float* Ws = sm + GROUP * XS;
    __shared__ int spr[GROUP], sjj[GROUP];

    const int t = threadIdx.x;
    const int w = t >> 5, lane = t & 31;
    const int rg = w & 1, cg = w >> 1;
    const int g = lane >> 2, tig = lane & 3;
    const int npairs = g_pair_count;
    const int units = ((npairs + GROUP - 1) / GROUP) * 2;

    for (int u = blockIdx.x; u < units; u += gridDim.x) {
        const int g0 = (u >> 1) * GROUP;
        const int ch = u & 1;
        if (t < GROUP) {
            if (g0 + t < npairs) {
                spr[t] = g_pairs[2 * (g0 + t)];
                sjj[t] = g_pairs[2 * (g0 + t) + 1];
            } else spr[t] = -1;
        }
        __syncthreads();

        // stage X = relu(P_i - P_j + b3) (full width)
#pragma unroll
        for (int i = 0; i < 8; i++) {
            const int idx = t + (i << 8);
            const int p = idx >> 6, c4 = (idx & 63) << 2;
            const int rp = spr[p];
            float4 v = make_float4(0.f, 0.f, 0.f, 0.f);
            if (rp >= 0) {
                const int jab = (rp / NQ) * NQ + sjj[p];
                const float4 a  = *(const float4*)(g_P + (size_t)rp  * D + c4);
                const float4 nb = *(const float4*)(g_P + (size_t)jab * D + c4);
                const float4 bv = *(const float4*)(b3 + c4);
                v.x = fmaxf(a.x - nb.x + bv.x, 0.f);
                v.y = fmaxf(a.y - nb.y + bv.y, 0.f);
                v.z = fmaxf(a.z - nb.z + bv.z, 0.f);
                v.w = fmaxf(a.w - nb.w + bv.w, 0.f);
            }
            *(float4*)(Xs + p * XS + c4) = v;
        }

        float C[4][4];
        mma_half(Xs, Ws, W4, ch, C, rg, cg, g, tig, t);

        // dump features into Xs (local col index within the half)
#pragma unroll
        for (int nt = 0; nt < 4; nt++) {
            const int colL = cg * 32 + nt * 8 + (tig << 1);
            const int p0 = rg * 16 + g, p1 = p0 + 8;
            *(float2*)(Xs + p0 * XS + colL) = make_float2(C[nt][0], C[nt][1]);
            *(float2*)(Xs + p1 * XS + colL) = make_float2(C[nt][2], C[nt][3]);
        }
        __syncthreads();

        // segmented max: thread t -> local col t&127, pair-range half t>>7
        {
            const int cL = t & 127;
            const int colG = ch * 128 + cL;
            const float bias = b4[colG];
            const int pLo = (t >> 7) << 4;      // 0 or 16
            int curRow = -1; float curMax = 0.f;
            for (int p = pLo; p < pLo + 16; p++) {
                const int rp = spr[p];
                if (rp < 0) break;
                const float v = Xs[p * XS + cL] + bias;
                if (rp != curRow) {
                    if (curRow >= 0) atomicMaxFloat(&g_cur[(size_t)curRow * D + colG], curMax);
                    curRow = rp; curMax = v;
                } else {
                    curMax = fmaxf(curMax, v);
                }
            }
            if (curRow >= 0) atomicMaxFloat(&g_cur[(size_t)curRow * D + colG], curMax);
        }
        __syncthreads();
    }
}

// ---------------- L5: out = tgt + relu(cur@W5+b5) for active rows ----------------
__global__ __launch_bounds__(256, 3) void k_l5(
    const float* __restrict__ tgt, const float* __restrict__ W5,
    const float* __restrict__ b5, float* __restrict__ out)
{
    extern __shared__ float sm[];
    float* Xs = sm;
    float* Ws = sm + GROUP * XS;
    __shared__ int srow[GROUP];

    const int t = threadIdx.x;
    const int w = t >> 5, lane = t & 31;
    const int rg = w & 1, cg = w >> 1;
    const int g = lane >> 2, tig = lane & 3;
    const int nact = g_nout;
    const int units = ((nact + GROUP - 1) / GROUP) * 2;

    for (int u = blockIdx.x; u < units; u += gridDim.x) {
        const int g0 = (u >> 1) * GROUP;
        const int ch = u & 1;
        if (t < GROUP) srow[t] = (g0 + t < nact) ? g_outrows[g0 + t] : -1;
        __syncthreads();
        stage_rows(Xs, g_cur, srow, t);

        float C[4][4];
        mma_half(Xs, Ws, W5, ch, C, rg, cg, g, tig, t);

#pragma unroll
        for (int nt = 0; nt < 4; nt++) {
            const int col = ch * 128 + cg * 32 + nt * 8 + (tig << 1);
            const float2 bb = *(const float2*)(b5 + col);
            const int r0 = rg * 16 + g, r1 = r0 + 8;
            const int rw0 = srow[r0], rw1 = srow[r1];
            if (rw0 >= 0) {
                const float2 tg = *(const float2*)(tgt + (size_t)rw0 * D + col);
                *(float2*)(out + (size_t)rw0 * D + col) =
                    make_float2(tg.x + fmaxf(C[nt][0] + bb.x, 0.f),
                                tg.y + fmaxf(C[nt][1] + bb.y, 0.f));
            }
            if (rw1 >= 0) {
                const float2 tg = *(const float2*)(tgt + (size_t)rw1 * D + col);
                *(float2*)(out + (size_t)rw1 * D + col) =
                    make_float2(tg.x + fmaxf(C[nt][2] + bb.x, 0.f),
                                tg.y + fmaxf(C[nt][3] + bb.y, 0.f));
            }
        }
        __syncthreads();
    }
}

// ---------------- launch ----------------
extern "C" void kernel_launch(void* const* d_in, const int* in_sizes, int n_in,
                              void* d_out, int out_size) {
    const float* tgt  = (const float*)d_in[0];
    const float* seed = (const float*)d_in[1];
    const float* pred = (const float*)d_in[2];
    const float* W1 = (const float*)d_in[3];  const float* b1 = (const float*)d_in[4];
    const float* W2 = (const float*)d_in[5];  const float* b2 = (const float*)d_in[6];
    const float* g2 = (const float*)d_in[7];  const float* be2 = (const float*)d_in[8];
    const float* W3 = (const float*)d_in[9];  const float* b3 = (const float*)d_in[10];
    const float* W4 = (const float*)d_in[11]; const float* b4 = (const float*)d_in[12];
    const float* W5 = (const float*)d_in[13]; const float* b5 = (const float*)d_in[14];

    float* out = (float*)d_out;                 // cur_tgt: 8*1000*256 floats
    float* out_mask = out + (size_t)NROWS * D;  // attn_mask: 8*1000*1000 floats

    cudaFuncSetAttribute(k_l1, cudaFuncAttributeMaxDynamicSharedMemorySize, SMEM_G);
    cudaFuncSetAttribute(k_l2, cudaFuncAttributeMaxDynamicSharedMemorySize, SMEM_G);
    cudaFuncSetAttribute(k_l3, cudaFuncAttributeMaxDynamicSharedMemorySize, SMEM_G);
    cudaFuncSetAttribute(k_l4, cudaFuncAttributeMaxDynamicSharedMemorySize, SMEM_G);
    cudaFuncSetAttribute(k_l5, cudaFuncAttributeMaxDynamicSharedMemorySize, SMEM_G);

    k_prep<<<(NROWS + 255) / 256, 256>>>();
    k_mask_sel<<<NROWS / MROWS, 256>>>(pred, seed, tgt, b5, out, out_mask);
    k_compact<<<(NROWS + 255) / 256, 256>>>();
    k_l1<<<GRID_G, 256, SMEM_G>>>(tgt, W1, b1);
    k_l2<<<GRID_G, 256, SMEM_G>>>(W2, b2);
    k_l3<<<GRID_G, 256, SMEM_G>>>(W3, g2, be2);
    k_l4<<<GRID_G, 256, SMEM_G>>>(W4, b3, b4);
    k_l5<<<GRID_G, 256, SMEM_G>>>(tgt, W5, b5, out);
}

// round 16
// speedup vs baseline: 1.5118x; 1.3340x over previous
#include <cuda_runtime.h>
#include <cuda_bf16.h>
#include <math_constants.h>
#include <cstdint>

#define BS 8
#define NQ 1000
#define D 256
#define NROWS (BS * NQ)
#define TOPK 10
#define MAX_PAIRS (NROWS * TOPK)
#define MROWS 10      // rows per block in mask kernel
#define GROUP 32      // rows/pairs per group in GEMM kernels
#define AST 132       // words per X-plane row (128 + 4 pad -> conflict-free)
#define WST 136       // words per W-buffer row (128 + 8 pad -> conflict-free)
#define KC 16         // k-values per staged chunk
#define NCHUNK (D / KC)
#define WBUF (16 * WST)      // words per staged W chunk (2 planes x 8 kpairs)
#define XPL (GROUP * AST)    // words per X plane (4224)
#define GRID_G 444
#define SMEM_G ((2 * XPL + 3 * WBUF) * 4)   // 59,904 bytes

// ---------------- scratch (no allocations allowed) ----------------
__device__ float g_H[NROWS * D];        // layer-1 output (active rows)
__device__ float g_Z[NROWS * D];        // layer-2 output (pre-LN)
__device__ float g_P[NROWS * D];        // P = id_token @ W3
__device__ float g_cur[NROWS * D];      // running max of masked features
__device__ __align__(16) uint32_t g_Wbf[5 * 65536];  // bf16 (h,l) planes, k-pair packed
__device__ int   g_pairs[MAX_PAIRS * 2];
__device__ int   g_pair_count;
__device__ int   g_flag[NROWS];
__device__ int   g_idrows[NROWS];
__device__ int   g_nid;
__device__ int   g_outrows[NROWS];
__device__ int   g_nout;

__device__ __forceinline__ void atomicMaxFloat(float* addr, float v) {
    if (v >= 0.0f) atomicMax((int*)addr, __float_as_int(v));
    else           atomicMin((unsigned int*)addr, __float_as_uint(v));
}

// ---------------- bf16 2-split helpers ----------------
// x = h + l (+ ~2^-17 |x|); words pack (even-k in low half, odd-k in high half)
__device__ __forceinline__ void split_bf16x2(float x0, float x1,
                                             uint32_t& wh, uint32_t& wl) {
    uint32_t wh_;
    asm("{\n\t.reg .b16 h0, h1;\n\t"
        "cvt.rn.bf16.f32 h0, %1;\n\t"
        "cvt.rn.bf16.f32 h1, %2;\n\t"
        "mov.b32 %0, {h0, h1};\n\t}" : "=r"(wh_) : "f"(x0), "f"(x1));
    const float h0f = __uint_as_float(wh_ << 16);
    const float h1f = __uint_as_float(wh_ & 0xffff0000u);
    const float l0 = x0 - h0f, l1 = x1 - h1f;
    uint32_t wl_;
    asm("{\n\t.reg .b16 p0, p1;\n\t"
        "cvt.rn.bf16.f32 p0, %1;\n\t"
        "cvt.rn.bf16.f32 p1, %2;\n\t"
        "mov.b32 %0, {p0, p1};\n\t}" : "=r"(wl_) : "f"(l0), "f"(l1));
    wh = wh_; wl = wl_;
}

__device__ __forceinline__ void mma_bf16(float c[4],
    uint32_t a0, uint32_t a1, uint32_t a2, uint32_t a3,
    uint32_t b0, uint32_t b1)
{
    asm volatile(
        "mma.sync.aligned.m16n8k16.row.col.f32.bf16.bf16.f32 "
        "{%0,%1,%2,%3}, {%4,%5,%6,%7}, {%8,%9}, {%0,%1,%2,%3};"
        : "+f"(c[0]), "+f"(c[1]), "+f"(c[2]), "+f"(c[3])
        : "r"(a0), "r"(a1), "r"(a2), "r"(a3), "r"(b0), "r"(b1));
}

// ---------------- cp.async helpers ----------------
__device__ __forceinline__ uint32_t smem_u32(const void* p) {
    return (uint32_t)__cvta_generic_to_shared(p);
}
__device__ __forceinline__ void cp16(uint32_t dst, const void* src) {
    asm volatile("cp.async.cg.shared.global [%0], [%1], 16;" :: "r"(dst), "l"(src));
}
__device__ __forceinline__ void cp_commit() {
    asm volatile("cp.async.commit_group;");
}
__device__ __forceinline__ void cp_wait0() {
    asm volatile("cp.async.wait_group 0;");
}
__device__ __forceinline__ void cp_wait1() {
    asm volatile("cp.async.wait_group 1;");
}

// ---------------- prep: reset + convert weights to bf16 planes ----------------
// g_Wbf layout per weight w (65536 words): plane p (h=0,l=1) at p*32768;
// word (kp, col) = base + kp*256 + col, packing (k=2kp low, k=2kp+1 high).
__global__ __launch_bounds__(256) void k_prep(
    const float* __restrict__ W1, const float* __restrict__ W2,
    const float* __restrict__ W3, const float* __restrict__ W4,
    const float* __restrict__ W5)
{
    const int idx = blockIdx.x * 256 + threadIdx.x;
    if (idx < NROWS) g_flag[idx] = 0;
    if (idx == 0) { g_pair_count = 0; g_nid = 0; g_nout = 0; }
    if (idx < 5 * 32768) {
        const int w = idx >> 15, rem = idx & 32767;
        const int kp = rem >> 8, col = rem & 255;
        const float* Wt[5] = {W1, W2, W3, W4, W5};
        const float x0 = Wt[w][(2 * kp) * D + col];
        const float x1 = Wt[w][(2 * kp + 1) * D + col];
        uint32_t wh, wl;
        split_bf16x2(x0, x1, wh, wl);
        g_Wbf[w * 65536 + kp * 256 + col] = wh;
        g_Wbf[w * 65536 + 32768 + kp * 256 + col] = wl;
    }
}

// stage one 16-k chunk (both planes) of one column-half of packed W
// 512 cp16 segments over 256 threads (2 each)
__device__ __forceinline__ void stage_w(uint32_t* Wbuf, const uint32_t* __restrict__ Wg,
                                        int kc, int ch, int t)
{
#pragma unroll
    for (int i = 0; i < 2; i++) {
        const int idx = t + (i << 8);          // 0..511
        const int p  = idx >> 8;               // plane
        const int r8 = (idx >> 5) & 7;         // kpair within chunk
        const int sg = idx & 31;               // 16B segment (4 words)
        cp16(smem_u32(Wbuf + (p * 8 + r8) * WST + (sg << 2)),
             Wg + (size_t)p * 32768 + (kc * 8 + r8) * 256 + (ch << 7) + (sg << 2));
    }
    cp_commit();
}

// Core: C[4][4] = X(32 x 256, bf16 2-split planes) @ W[:, ch*128..+128), bf16x3.
// 8 warps: rg = w&1 (16-row group), cg = w>>1 (32-col group within half).
__device__ __forceinline__ void mma_half(
    const uint32_t* Xsh, const uint32_t* Xsl, uint32_t* Ws,
    const uint32_t* __restrict__ Wg, int ch,
    float C[4][4], int rg, int cg, int g, int tig, int t)
{
#pragma unroll
    for (int nt = 0; nt < 4; nt++)
#pragma unroll
        for (int i = 0; i < 4; i++) C[nt][i] = 0.0f;

    const int row0 = rg * 16 + g;

    stage_w(Ws,        Wg, 0, ch, t);
    stage_w(Ws + WBUF, Wg, 1, ch, t);
    for (int kc = 0; kc < NCHUNK; kc++) {
        if (kc == NCHUNK - 1) cp_wait0(); else cp_wait1();
        __syncthreads();   // chunk kc visible; restaged buffer free; (kc=0) X writes ordered
        if (kc + 2 < NCHUNK) stage_w(Ws + ((kc + 2) % 3) * WBUF, Wg, kc + 2, ch, t);
        const uint32_t* Wb = Ws + (kc % 3) * WBUF;

        const int ab = row0 * AST + kc * 8 + tig;
        const uint32_t ah0 = Xsh[ab];
        const uint32_t ah1 = Xsh[ab + 8 * AST];
        const uint32_t ah2 = Xsh[ab + 4];
        const uint32_t ah3 = Xsh[ab + 8 * AST + 4];
        const uint32_t al0 = Xsl[ab];
        const uint32_t al1 = Xsl[ab + 8 * AST];
        const uint32_t al2 = Xsl[ab + 4];
        const uint32_t al3 = Xsl[ab + 8 * AST + 4];

#pragma unroll
        for (int nt = 0; nt < 4; nt++) {
            const int col = cg * 32 + nt * 8 + g;
            const uint32_t bh0 = Wb[tig * WST + col];
            const uint32_t bh1 = Wb[(tig + 4) * WST + col];
            const uint32_t bl0 = Wb[(8 + tig) * WST + col];
            const uint32_t bl1 = Wb[(12 + tig) * WST + col];
            mma_bf16(C[nt], ah0, ah1, ah2, ah3, bh0, bh1);
            mma_bf16(C[nt], ah0, ah1, ah2, ah3, bl0, bl1);
            mma_bf16(C[nt], al0, al1, al2, al3, bh0, bh1);
        }
    }
    __syncthreads();   // all warps done before caller reuses X/W regions
}

// stage 32 indexed rows (guarded) as split planes
__device__ __forceinline__ void stage_rows_cvt(uint32_t* Xsh, uint32_t* Xsl,
                                               const float* __restrict__ src,
                                               const int* srow, int t)
{
#pragma unroll
    for (int i = 0; i < 8; i++) {
        const int idx = t + (i << 8);
        const int r = idx >> 6, c4 = (idx & 63) << 2;
        const int rr = srow[r];
        const float4 v = (rr >= 0) ? *(const float4*)(src + (size_t)rr * D + c4)
                                   : make_float4(0.f, 0.f, 0.f, 0.f);
        uint32_t h0, l0, h1, l1;
        split_bf16x2(v.x, v.y, h0, l0);
        split_bf16x2(v.z, v.w, h1, l1);
        const int wi = r * AST + (c4 >> 1);
        *(uint2*)&Xsh[wi] = make_uint2(h0, h1);
        *(uint2*)&Xsl[wi] = make_uint2(l0, l1);
    }
}

// ---------------- K2: IoU mask + selection + cur-init + base output ----------------
__global__ __launch_bounds__(256) void k_mask_sel(
    const float* __restrict__ pred, const float* __restrict__ seed,
    const float* __restrict__ tgt,  const float* __restrict__ b5,
    float* __restrict__ out, float* __restrict__ out_mask)
{
    const int base = blockIdx.x * MROWS;
    const int b = base / NQ;
    const int t = threadIdx.x;

    __shared__ float4 s_box[NQ];
    __shared__ float  s_seed[NQ];
    __shared__ int    s_cnt, s_m;
    __shared__ float  sval[256];
    __shared__ int    sidx[256];

    const float rb5 = fmaxf(b5[t], 0.0f);

    for (int j = t; j < NQ; j += 256) {
        s_box[j]  = ((const float4*)pred)[b * NQ + j];
        s_seed[j] = seed[b * NQ + j];
    }
    __syncthreads();

    for (int r = 0; r < MROWS; r++) {
        const int row = base + r;
        const int li  = row - b * NQ;
        if (t == 0) s_cnt = 0;
        __syncthreads();

        const float4 pb = s_box[li];
        const float bx1 = __fsub_rn(pb.x, __fmul_rn(0.5f, pb.z));
        const float by1 = __fsub_rn(pb.y, __fmul_rn(0.5f, pb.w));
        const float bx2 = __fadd_rn(pb.x, __fmul_rn(0.5f, pb.z));
        const float by2 = __fadd_rn(pb.y, __fmul_rn(0.5f, pb.w));
        const float ai  = __fmul_rn(__fsub_rn(bx2, bx1), __fsub_rn(by2, by1));
        const bool negi = (s_seed[li] == 0.0f);

        for (int j = t; j < NQ; j += 256) {
            const float4 q = s_box[j];
            const float qx1 = __fsub_rn(q.x, __fmul_rn(0.5f, q.z));
            const float qy1 = __fsub_rn(q.y, __fmul_rn(0.5f, q.w));
            const float qx2 = __fadd_rn(q.x, __fmul_rn(0.5f, q.z));
            const float qy2 = __fadd_rn(q.y, __fmul_rn(0.5f, q.w));
            const float aj  = __fmul_rn(__fsub_rn(qx2, qx1), __fsub_rn(qy2, qy1));
            const float w = fmaxf(__fsub_rn(fminf(bx2, qx2), fmaxf(bx1, qx1)), 0.0f);
            const float h = fmaxf(__fsub_rn(fminf(by2, qy2), fmaxf(by1, qy1)), 0.0f);
            const float inter = __fmul_rn(w, h);
            const float uni = __fsub_rn(__fadd_rn(ai, aj), inter);
            const float iou = __fdiv_rn(inter, uni);
            const bool attn = (iou >= 0.5f);
            out_mask[(size_t)row * NQ + j] = attn ? 1.0f : 0.0f;
            if (attn && negi && (s_seed[j] != 0.0f)) {
                int p = atomicAdd(&s_cnt, 1);
                if (p < 256) { sval[p] = iou; sidx[p] = j; }
            }
        }
        __syncthreads();

        if (t == 0) {
            int cnt = min(s_cnt, 256);
            int m;
            int sel[TOPK];
            if (cnt <= TOPK) {
                m = cnt;
                for (int qq = 0; qq < cnt; qq++) sel[qq] = sidx[qq];
            } else {
                m = TOPK;
                for (int rr = 0; rr < TOPK; rr++) {
                    float best = -1.0f; int bj = 0x7fffffff; int bp = -1;
                    for (int p = 0; p < cnt; p++) {
                        float v = sval[p]; int j = sidx[p];
                        if (v > best || (v == best && j < bj)) { best = v; bj = j; bp = p; }
                    }
                    sel[rr] = bj;
                    sval[bp] = -1.0f;
                }
            }
            s_m = m;
            if (m > 0) {
                int pbase = atomicAdd(&g_pair_count, m);
                for (int qq = 0; qq < m; qq++) {
                    g_pairs[2 * (pbase + qq)]     = row;
                    g_pairs[2 * (pbase + qq) + 1] = sel[qq];
                    g_flag[b * NQ + sel[qq]] = 1;
                }
                g_flag[row] = 1;
                int op = atomicAdd(&g_nout, 1);
                g_outrows[op] = row;
            }
        }
        __syncthreads();
        const int m = s_m;
        if (m == 0) {
            const float neg = 1.0f - s_seed[li];
            out[(size_t)row * D + t] = tgt[(size_t)row * D + t] + rb5 * neg;
        } else {
            g_cur[(size_t)row * D + t] = (m < TOPK) ? 0.0f : -CUDART_INF_F;
        }
    }
}

// ---------------- compaction of id-rows ----------------
__global__ void k_compact() {
    const int i = blockIdx.x * 256 + threadIdx.x;
    if (i < NROWS && g_flag[i]) {
        int p = atomicAdd(&g_nid, 1);
        g_idrows[p] = i;
    }
}

// ---------------- L1: h = relu(tgt@W1 + b1) ----------------
__global__ __launch_bounds__(256, 3) void k_l1(
    const float* __restrict__ tgt, const float* __restrict__ b1)
{
    extern __shared__ uint32_t sm[];
    uint32_t* Xsh = sm;
    uint32_t* Xsl = sm + XPL;
    uint32_t* Ws  = sm + 2 * XPL;
    __shared__ int srow[GROUP];

    const int t = threadIdx.x;
    const int w = t >> 5, lane = t & 31;
    const int rg = w & 1, cg = w >> 1;
    const int g = lane >> 2, tig = lane & 3;
    const int nact = g_nid;
    const int units = ((nact + GROUP - 1) / GROUP) * 2;

    for (int u = blockIdx.x; u < units; u += gridDim.x) {
        const int g0 = (u >> 1) * GROUP;
        const int ch = u & 1;
        if (t < GROUP) srow[t] = (g0 + t < nact) ? g_idrows[g0 + t] : -1;
        __syncthreads();
        stage_rows_cvt(Xsh, Xsl, tgt, srow, t);

        float C[4][4];
        mma_half(Xsh, Xsl, Ws, g_Wbf, ch, C, rg, cg, g, tig, t);

#pragma unroll
        for (int nt = 0; nt < 4; nt++) {
            const int col = ch * 128 + cg * 32 + nt * 8 + (tig << 1);
            const float2 bb = *(const float2*)(b1 + col);
            const int r0 = rg * 16 + g, r1 = r0 + 8;
            const int rw0 = srow[r0], rw1 = srow[r1];
            if (rw0 >= 0)
                *(float2*)(g_H + (size_t)rw0 * D + col) =
                    make_float2(fmaxf(C[nt][0] + bb.x, 0.f), fmaxf(C[nt][1] + bb.y, 0.f));
            if (rw1 >= 0)
                *(float2*)(g_H + (size_t)rw1 * D + col) =
                    make_float2(fmaxf(C[nt][2] + bb.x, 0.f), fmaxf(C[nt][3] + bb.y, 0.f));
        }
        __syncthreads();
    }
}

// ---------------- L2: z = h@W2 + b2 ----------------
__global__ __launch_bounds__(256, 3) void k_l2(const float* __restrict__ b2)
{
    extern __shared__ uint32_t sm[];
    uint32_t* Xsh = sm;
    uint32_t* Xsl = sm + XPL;
    uint32_t* Ws  = sm + 2 * XPL;
    __shared__ int srow[GROUP];

    const int t = threadIdx.x;
    const int w = t >> 5, lane = t & 31;
    const int rg = w & 1, cg = w >> 1;
    const int g = lane >> 2, tig = lane & 3;
    const int nact = g_nid;
    const int units = ((nact + GROUP - 1) / GROUP) * 2;

    for (int u = blockIdx.x; u < units; u += gridDim.x) {
        const int g0 = (u >> 1) * GROUP;
        const int ch = u & 1;
        if (t < GROUP) srow[t] = (g0 + t < nact) ? g_idrows[g0 + t] : -1;
        __syncthreads();
        stage_rows_cvt(Xsh, Xsl, g_H, srow, t);

        float C[4][4];
        mma_half(Xsh, Xsl, Ws, g_Wbf + 65536, ch, C, rg, cg, g, tig, t);

#pragma unroll
        for (int nt = 0; nt < 4; nt++) {
            const int col = ch * 128 + cg * 32 + nt * 8 + (tig << 1);
            const float2 bb = *(const float2*)(b2 + col);
            const int r0 = rg * 16 + g, r1 = r0 + 8;
            const int rw0 = srow[r0], rw1 = srow[r1];
            if (rw0 >= 0)
                *(float2*)(g_Z + (size_t)rw0 * D + col) =
                    make_float2(C[nt][0] + bb.x, C[nt][1] + bb.y);
            if (rw1 >= 0)
                *(float2*)(g_Z + (size_t)rw1 * D + col) =
                    make_float2(C[nt][2] + bb.x, C[nt][3] + bb.y);
        }
        __syncthreads();
    }
}

// ---------------- L3: P = (LN(z)*g2+be2) @ W3 ----------------
__global__ __launch_bounds__(256, 3) void k_l3(
    const float* __restrict__ g2, const float* __restrict__ be2)
{
    extern __shared__ uint32_t sm[];
    uint32_t* Xsh = sm;
    uint32_t* Xsl = sm + XPL;
    uint32_t* Ws  = sm + 2 * XPL;
    __shared__ int srow[GROUP];
    __shared__ float s_mean[GROUP], s_rstd[GROUP];

    const int t = threadIdx.x;
    const int w = t >> 5, lane = t & 31;
    const int rg = w & 1, cg = w >> 1;
    const int g = lane >> 2, tig = lane & 3;
    const int nact = g_nid;
    const int units = ((nact + GROUP - 1) / GROUP) * 2;

    for (int u = blockIdx.x; u < units; u += gridDim.x) {
        const int g0 = (u >> 1) * GROUP;
        const int ch = u & 1;
        if (t < GROUP) srow[t] = (g0 + t < nact) ? g_idrows[g0 + t] : -1;
        __syncthreads();

        // LN stats straight from global: warp w rows 4w..4w+3
        for (int rr = (w << 2); rr < (w << 2) + 4; rr++) {
            const int row = srow[rr];
            float s = 0.f, sq = 0.f;
            if (row >= 0) {
#pragma unroll
                for (int i = 0; i < 2; i++) {
                    const float4 v = *(const float4*)(g_Z + (size_t)row * D + (lane << 2) + (i << 7));
                    s += v.x + v.y + v.z + v.w;
                    sq += v.x * v.x + v.y * v.y + v.z * v.z + v.w * v.w;
                }
            }
#pragma unroll
            for (int off = 16; off > 0; off >>= 1) {
                s  += __shfl_down_sync(0xffffffff, s,  off);
                sq += __shfl_down_sync(0xffffffff, sq, off);
            }
            if (lane == 0) {
                const float m = s * (1.0f / D);
                s_mean[rr] = m;
                s_rstd[rr] = rsqrtf(sq * (1.0f / D) - m * m + 1e-5f);
            }
        }
        __syncthreads();

        // stage rows with LN transform applied, converting to planes
#pragma unroll
        for (int i = 0; i < 8; i++) {
            const int idx = t + (i << 8);
            const int r = idx >> 6, c4 = (idx & 63) << 2;
            const int rr = srow[r];
            float4 v = make_float4(0.f, 0.f, 0.f, 0.f);
            if (rr >= 0) {
                const float4 z = *(const float4*)(g_Z + (size_t)rr * D + c4);
                const float4 gv = *(const float4*)(g2 + c4);
                const float4 bv = *(const float4*)(be2 + c4);
                const float m = s_mean[r], rs = s_rstd[r];
                v.x = (z.x - m) * rs * gv.x + bv.x;
                v.y = (z.y - m) * rs * gv.y + bv.y;
                v.z = (z.z - m) * rs * gv.z + bv.z;
                v.w = (z.w - m) * rs * gv.w + bv.w;
            }
            uint32_t h0, l0, h1, l1;
            split_bf16x2(v.x, v.y, h0, l0);
            split_bf16x2(v.z, v.w, h1, l1);
            const int wi = r * AST + (c4 >> 1);
            *(uint2*)&Xsh[wi] = make_uint2(h0, h1);
            *(uint2*)&Xsl[wi] = make_uint2(l0, l1);
        }

        float C[4][4];
        mma_half(Xsh, Xsl, Ws, g_Wbf + 2 * 65536, ch, C, rg, cg, g, tig, t);

#pragma unroll
        for (int nt = 0; nt < 4; nt++) {
            const int col = ch * 128 + cg * 32 + nt * 8 + (tig << 1);
            const int r0 = rg * 16 + g, r1 = r0 + 8;
            const int rw0 = srow[r0], rw1 = srow[r1];
            if (rw0 >= 0)
                *(float2*)(g_P + (size_t)rw0 * D + col) = make_float2(C[nt][0], C[nt][1]);
            if (rw1 >= 0)
                *(float2*)(g_P + (size_t)rw1 * D + col) = make_float2(C[nt][2], C[nt][3]);
        }
        __syncthreads();
    }
}

// ---------------- L4: per-pair relu(P_i-P_j+b3)@W4+b4 -> seg-max + atomic ----------------
__global__ __launch_bounds__(256, 3) void k_l4(
    const float* __restrict__ b3, const float* __restrict__ b4)
{
    extern __shared__ uint32_t sm[];
    uint32_t* Xsh = sm;
    uint32_t* Xsl = sm + XPL;
    uint32_t* Ws  = sm + 2 * XPL;
    float* scratch = (float*)sm;   // reused after MMA for feature dump
    __shared__ int spr[GROUP], sjj[GROUP];

    const int t = threadIdx.x;
    const int w = t >> 5, lane = t & 31;
    const int rg = w & 1, cg = w >> 1;
    const int g = lane >> 2, tig = lane & 3;
    const int npairs = g_pair_count;
    const int units = ((npairs + GROUP - 1) / GROUP) * 2;

    for (int u = blockIdx.x; u < units; u += gridDim.x) {
        const int g0 = (u >> 1) * GROUP;
        const int ch = u & 1;
        if (t < GROUP) {
            if (g0 + t < npairs) {
                spr[t] = g_pairs[2 * (g0 + t)];
                sjj[t] = g_pairs[2 * (g0 + t) + 1];
            } else spr[t] = -1;
        }
        __syncthreads();

        // stage X = relu(P_i - P_j + b3), converting to planes
#pragma unroll
        for (int i = 0; i < 8; i++) {
            const int idx = t + (i << 8);
            const int p = idx >> 6, c4 = (idx & 63) << 2;
            const int rp = spr[p];
            float4 v = make_float4(0.f, 0.f, 0.f, 0.f);
            if (rp >= 0) {
                const int jab = (rp / NQ) * NQ + sjj[p];
                const float4 a  = *(const float4*)(g_P + (size_t)rp  * D + c4);
                const float4 nb = *(const float4*)(g_P + (size_t)jab * D + c4);
                const float4 bv = *(const float4*)(b3 + c4);
                v.x = fmaxf(a.x - nb.x + bv.x, 0.f);
                v.y = fmaxf(a.y - nb.y + bv.y, 0.f);
                v.z = fmaxf(a.z - nb.z + bv.z, 0.f);
                v.w = fmaxf(a.w - nb.w + bv.w, 0.f);
            }
            uint32_t h0, l0, h1, l1;
            split_bf16x2(v.x, v.y, h0, l0);
            split_bf16x2(v.z, v.w, h1, l1);
            const int wi = p * AST + (c4 >> 1);
            *(uint2*)&Xsh[wi] = make_uint2(h0, h1);
            *(uint2*)&Xsl[wi] = make_uint2(l0, l1);
        }

        float C[4][4];
        mma_half(Xsh, Xsl, Ws, g_Wbf + 3 * 65536, ch, C, rg, cg, g, tig, t);

        // dump features into scratch (local col within half, stride AST)
#pragma unroll
        for (int nt = 0; nt < 4; nt++) {
            const int colL = cg * 32 + nt * 8 + (tig << 1);
            const int p0 = rg * 16 + g, p1 = p0 + 8;
            *(float2*)(scratch + p0 * AST + colL) = make_float2(C[nt][0], C[nt][1]);
            *(float2*)(scratch + p1 * AST + colL) = make_float2(C[nt][2], C[nt][3]);
        }
        __syncthreads();

        // segmented max: thread t -> local col t&127, pair-range half t>>7
        {
            const int cL = t & 127;
            const int colG = ch * 128 + cL;
            const float bias = b4[colG];
            const int pLo = (t >> 7) << 4;      // 0 or 16
            int curRow = -1; float curMax = 0.f;
            for (int p = pLo; p < pLo + 16; p++) {
                const int rp = spr[p];
                if (rp < 0) break;
                const float v = scratch[p * AST + cL] + bias;
                if (rp != curRow) {
                    if (curRow >= 0) atomicMaxFloat(&g_cur[(size_t)curRow * D + colG], curMax);
                    curRow = rp; curMax = v;
                } else {
                    curMax = fmaxf(curMax, v);
                }
            }
            if (curRow >= 0) atomicMaxFloat(&g_cur[(size_t)curRow * D + colG], curMax);
        }
        __syncthreads();
    }
}

// ---------------- L5: out = tgt + relu(cur@W5+b5) for active rows ----------------
__global__ __launch_bounds__(256, 3) void k_l5(
    const float* __restrict__ tgt, const float* __restrict__ b5,
    float* __restrict__ out)
{
    extern __shared__ uint32_t sm[];
    uint32_t* Xsh = sm;
    uint32_t* Xsl = sm + XPL;
    uint32_t* Ws  = sm + 2 * XPL;
    __shared__ int srow[GROUP];

    const int t = threadIdx.x;
    const int w = t >> 5, lane = t & 31;
    const int rg = w & 1, cg = w >> 1;
    const int g = lane >> 2, tig = lane & 3;
    const int nact = g_nout;
    const int units = ((nact + GROUP - 1) / GROUP) * 2;

    for (int u = blockIdx.x; u < units; u += gridDim.x) {
        const int g0 = (u >> 1) * GROUP;
        const int ch = u & 1;
        if (t < GROUP) srow[t] = (g0 + t < nact) ? g_outrows[g0 + t] : -1;
        __syncthreads();
        stage_rows_cvt(Xsh, Xsl, g_cur, srow, t);

        float C[4][4];
        mma_half(Xsh, Xsl, Ws, g_Wbf + 4 * 65536, ch, C, rg, cg, g, tig, t);

#pragma unroll
        for (int nt = 0; nt < 4; nt++) {
            const int col = ch * 128 + cg * 32 + nt * 8 + (tig << 1);
            const float2 bb = *(const float2*)(b5 + col);
            const int r0 = rg * 16 + g, r1 = r0 + 8;
            const int rw0 = srow[r0], rw1 = srow[r1];
            if (rw0 >= 0) {
                const float2 tg = *(const float2*)(tgt + (size_t)rw0 * D + col);
                *(float2*)(out + (size_t)rw0 * D + col) =
                    make_float2(tg.x + fmaxf(C[nt][0] + bb.x, 0.f),
                                tg.y + fmaxf(C[nt][1] + bb.y, 0.f));
            }
            if (rw1 >= 0) {
                const float2 tg = *(const float2*)(tgt + (size_t)rw1 * D + col);
                *(float2*)(out + (size_t)rw1 * D + col) =
                    make_float2(tg.x + fmaxf(C[nt][2] + bb.x, 0.f),
                                tg.y + fmaxf(C[nt][3] + bb.y, 0.f));
            }
        }
        __syncthreads();
    }
}

// ---------------- launch ----------------
extern "C" void kernel_launch(void* const* d_in, const int* in_sizes, int n_in,
                              void* d_out, int out_size) {
    const float* tgt  = (const float*)d_in[0];
    const float* seed = (const float*)d_in[1];
    const float* pred = (const float*)d_in[2];
    const float* W1 = (const float*)d_in[3];  const float* b1 = (const float*)d_in[4];
    const float* W2 = (const float*)d_in[5];  const float* b2 = (const float*)d_in[6];
    const float* g2 = (const float*)d_in[7];  const float* be2 = (const float*)d_in[8];
    const float* W3 = (const float*)d_in[9];  const float* b3 = (const float*)d_in[10];
    const float* W4 = (const float*)d_in[11]; const float* b4 = (const float*)d_in[12];
    const float* W5 = (const float*)d_in[13]; const float* b5 = (const float*)d_in[14];

    float* out = (float*)d_out;                 // cur_tgt: 8*1000*256 floats
    float* out_mask = out + (size_t)NROWS * D;  // attn_mask: 8*1000*1000 floats

    cudaFuncSetAttribute(k_l1, cudaFuncAttributeMaxDynamicSharedMemorySize, SMEM_G);
    cudaFuncSetAttribute(k_l2, cudaFuncAttributeMaxDynamicSharedMemorySize, SMEM_G);
    cudaFuncSetAttribute(k_l3, cudaFuncAttributeMaxDynamicSharedMemorySize, SMEM_G);
    cudaFuncSetAttribute(k_l4, cudaFuncAttributeMaxDynamicSharedMemorySize, SMEM_G);
    cudaFuncSetAttribute(k_l5, cudaFuncAttributeMaxDynamicSharedMemorySize, SMEM_G);

    k_prep<<<(5 * 32768 + 255) / 256, 256>>>(W1, W2, W3, W4, W5);
    k_mask_sel<<<NROWS / MROWS, 256>>>(pred, seed, tgt, b5, out, out_mask);
    k_compact<<<(NROWS + 255) / 256, 256>>>();
    k_l1<<<GRID_G, 256, SMEM_G>>>(tgt, b1);
    k_l2<<<GRID_G, 256, SMEM_G>>>(b2);
    k_l3<<<GRID_G, 256, SMEM_G>>>(g2, be2);
    k_l4<<<GRID_G, 256, SMEM_G>>>(b3, b4);
    k_l5<<<GRID_G, 256, SMEM_G>>>(tgt, b5, out);
}